// round 10
// baseline (speedup 1.0000x reference)
#include <cuda_runtime.h>
#include <cuda_fp16.h>
#include <cuda_bf16.h>
#include <math_constants.h>

#define N_NODES 50000
#define N_EDGES 1600000
#define IN_SIZE 128
#define NUM_HEADS 4
#define OUT_SIZE 32
// H*D = 128 per node

typedef unsigned long long ull;

// Scratch (device globals — no allocation allowed)
__device__ __half g_h[(size_t)N_NODES * 128];   // projected features fp16 [N,128]
__device__ int    g_rowptr[N_NODES + 1];        // CSR offsets over sorted dst
__device__ ull    g_Wint[64 * 128];             // W interleaved: [k2][c] = (W[2k2][c], W[2k2+1][c])

// ---------------------------------------------------------------------------
// f32x2 helpers (sm_103a; ptxas never auto-fuses — PTX only)
// ---------------------------------------------------------------------------
__device__ __forceinline__ ull fma2(ull a, ull b, ull c) {
    ull d;
    asm("fma.rn.f32x2 %0, %1, %2, %3;" : "=l"(d) : "l"(a), "l"(b), "l"(c));
    return d;
}
__device__ __forceinline__ float2 unpack2(ull u) {
    float2 f;
    f.x = __int_as_float((int)(u & 0xffffffffull));
    f.y = __int_as_float((int)(u >> 32));
    return f;
}
__device__ __forceinline__ unsigned int h2_as_u32(__half2 h) {
    union { __half2 h; unsigned int u; } cvt;
    cvt.h = h;
    return cvt.u;
}

// ---------------------------------------------------------------------------
// Kernel 0: interleave W rows pairwise so the GEMM's f32x2 multiplier is a
// single natural 8B load: g_Wint[k2*128+c] = (W[2k2][c], W[2k2+1][c]).
// 64KB, L1-resident during GEMM. One-time ~1us.
// ---------------------------------------------------------------------------
__global__ void wint_kernel(const float* __restrict__ W) {
    const int idx = blockIdx.x * blockDim.x + threadIdx.x;  // 0..8191
    if (idx >= 64 * 128) return;
    const int k2 = idx >> 7;
    const int c = idx & 127;
    const unsigned int lo = __float_as_uint(__ldg(&W[(2 * k2) * 128 + c]));
    const unsigned int hi = __float_as_uint(__ldg(&W[(2 * k2 + 1) * 128 + c]));
    g_Wint[idx] = (ull)lo | ((ull)hi << 32);
}

// ---------------------------------------------------------------------------
// Kernel 1: h = feat @ W  (50000x128 @ 128x128), fp32 accum via k-split f32x2,
// fp16 output. Block = 256 threads (8 warps), 32 nodes/block; warp owns 4
// nodes; lane l owns cols 4l..4l+3. Accumulator lanes hold even-k / odd-k
// partial sums (combined by one FADD at the end) so BOTH fma2 operands come
// straight from memory: feat pair = LDS.64 broadcast, W pair = g_Wint LDG.
// No packing MOVs -> per k2: 4 LDS + 2 LDG + 16 FFMA2 ~= 23 issue slots for
// 32 fma-pipe cycles -> pipe-bound (~22us chip floor).
// ---------------------------------------------------------------------------
__global__ void __launch_bounds__(256) gemm_kernel(const float* __restrict__ feat) {
    __shared__ float sfeat[32][128];   // 16KB
    const int base = blockIdx.x * 32;
    const int tid = threadIdx.x;

    const int nvalid = min(32, N_NODES - base);
    const float4* fsrc = (const float4*)(feat + (size_t)base * 128);
    for (int i = tid; i < nvalid * 32; i += 256) ((float4*)sfeat)[i] = fsrc[i];
    __syncthreads();

    const int w = tid >> 5;   // warp -> nodes base+4w .. base+4w+3
    const int l = tid & 31;   // lane -> cols 4l..4l+3

    ull acc[4][4];
#pragma unroll
    for (int n = 0; n < 4; n++)
#pragma unroll
        for (int c = 0; c < 4; c++) acc[n][c] = 0ull;

    const ull* __restrict__ sf = (const ull*)&sfeat[0][0];       // sf[n*64 + k2]
    const ulonglong2* __restrict__ Wp = (const ulonglong2*)g_Wint; // [k2*64 + 2l]

#pragma unroll 8
    for (int k2 = 0; k2 < 64; k2++) {
        const ulonglong2 wv0 = __ldg(&Wp[k2 * 64 + 2 * l]);      // cols 4l, 4l+1
        const ulonglong2 wv1 = __ldg(&Wp[k2 * 64 + 2 * l + 1]);  // cols 4l+2, 4l+3
#pragma unroll
        for (int n = 0; n < 4; n++) {
            const ull f = sf[(w * 4 + n) * 64 + k2];  // (feat[2k2], feat[2k2+1]) broadcast
            acc[n][0] = fma2(f, wv0.x, acc[n][0]);
            acc[n][1] = fma2(f, wv0.y, acc[n][1]);
            acc[n][2] = fma2(f, wv1.x, acc[n][2]);
            acc[n][3] = fma2(f, wv1.y, acc[n][3]);
        }
    }

#pragma unroll
    for (int n = 0; n < 4; n++) {
        const int node = base + w * 4 + n;
        if (node < N_NODES) {
            float r[4];
#pragma unroll
            for (int c = 0; c < 4; c++) {
                const float2 v = unpack2(acc[n][c]);
                r[c] = v.x + v.y;   // even-k + odd-k partials
            }
            uint2 o;
            o.x = h2_as_u32(__floats2half2_rn(r[0], r[1]));
            o.y = h2_as_u32(__floats2half2_rn(r[2], r[3]));
            ((uint2*)g_h)[node * 32 + l] = o;
        }
    }
}

// ---------------------------------------------------------------------------
// Kernel 2: CSR offsets via binary search (dst is sorted).
// ---------------------------------------------------------------------------
__global__ void rowptr_kernel(const int* __restrict__ dst) {
    const int n = blockIdx.x * blockDim.x + threadIdx.x;
    if (n > N_NODES) return;
    int lo = 0, hi = N_EDGES;
    while (lo < hi) {
        const int mid = (lo + hi) >> 1;
        if (__ldg(&dst[mid]) < n) lo = mid + 1;
        else hi = mid;
    }
    g_rowptr[n] = lo;
}

// ---------------------------------------------------------------------------
// Kernel 3: fused scores + softmax + aggregation. One warp per dst node,
// 64-thread blocks (2 warps) to cut Poisson-degree imbalance at CTA scope.
// fp16 gathers (256B/warp/edge), fp32 math. hd pre-scaled by log2e/sqrt(D)
// so exp = single EX2. Explicit 4-deep gather pipeline for MLP.
// ---------------------------------------------------------------------------
__global__ void __launch_bounds__(64) attn_kernel(const int* __restrict__ src,
                                                  float* __restrict__ out) {
    const int n = (int)((blockIdx.x * blockDim.x + threadIdx.x) >> 5);
    const int l = threadIdx.x & 31;
    if (n >= N_NODES) return;

    const int beg = g_rowptr[n];
    const int end = g_rowptr[n + 1];

    const uint2* __restrict__ H2 = (const uint2*)g_h;

    // 1/sqrt(32) * log2(e): fold softmax scale + exp2 conversion into hd
    const float scale_d = 0.17677669529663689f * 1.4426950408889634f;
    float2 hd0, hd1;
    {
        const uint2 v = H2[n * 32 + l];
        const float2 a = __half22float2(*(const half2*)&v.x);
        const float2 b = __half22float2(*(const half2*)&v.y);
        hd0.x = a.x * scale_d; hd0.y = a.y * scale_d;
        hd1.x = b.x * scale_d; hd1.y = b.y * scale_d;
    }

    float s = 0.f;
    float2 acc0 = make_float2(0.f, 0.f);
    float2 acc1 = make_float2(0.f, 0.f);

    int e = beg;
    for (; e + 4 <= end; e += 4) {
        int sn[4];
#pragma unroll
        for (int j = 0; j < 4; j++) sn[j] = __ldg(&src[e + j]);
        uint2 v[4];
#pragma unroll
        for (int j = 0; j < 4; j++) v[j] = __ldg(&H2[sn[j] * 32 + l]);
#pragma unroll
        for (int j = 0; j < 4; j++) {
            const float2 a = __half22float2(*(const half2*)&v[j].x);
            const float2 b = __half22float2(*(const half2*)&v[j].y);
            float d = a.x * hd0.x;
            d = fmaf(a.y, hd0.y, d);
            d = fmaf(b.x, hd1.x, d);
            d = fmaf(b.y, hd1.y, d);
            d += __shfl_xor_sync(0xffffffffu, d, 1);
            d += __shfl_xor_sync(0xffffffffu, d, 2);
            d += __shfl_xor_sync(0xffffffffu, d, 4);
            const float p = exp2f(d);   // single MUFU.EX2
            s += p;
            acc0.x = fmaf(p, a.x, acc0.x);
            acc0.y = fmaf(p, a.y, acc0.y);
            acc1.x = fmaf(p, b.x, acc1.x);
            acc1.y = fmaf(p, b.y, acc1.y);
        }
    }
    for (; e < end; e++) {
        const int sn = __ldg(&src[e]);
        const uint2 v = __ldg(&H2[sn * 32 + l]);
        const float2 a = __half22float2(*(const half2*)&v.x);
        const float2 b = __half22float2(*(const half2*)&v.y);
        float d = a.x * hd0.x;
        d = fmaf(a.y, hd0.y, d);
        d = fmaf(b.x, hd1.x, d);
        d = fmaf(b.y, hd1.y, d);
        d += __shfl_xor_sync(0xffffffffu, d, 1);
        d += __shfl_xor_sync(0xffffffffu, d, 2);
        d += __shfl_xor_sync(0xffffffffu, d, 4);
        const float p = exp2f(d);
        s += p;
        acc0.x = fmaf(p, a.x, acc0.x);
        acc0.y = fmaf(p, a.y, acc0.y);
        acc1.x = fmaf(p, b.x, acc1.x);
        acc1.y = fmaf(p, b.y, acc1.y);
    }

    const float inv = (s > 0.f) ? (1.0f / s) : 0.f;
    float4 o;
    o.x = acc0.x * inv; o.y = acc0.y * inv;
    o.z = acc1.x * inv; o.w = acc1.y * inv;
    ((float4*)out)[n * 32 + l] = o;
}

// ---------------------------------------------------------------------------
extern "C" void kernel_launch(void* const* d_in, const int* in_sizes, int n_in,
                              void* d_out, int out_size) {
    const float* feat = (const float*)d_in[0];   // [N, 128] f32
    const int*   src  = (const int*)d_in[1];     // [E] i32
    const int*   dst  = (const int*)d_in[2];     // [E] i32, sorted
    const float* W    = (const float*)d_in[3];   // [128, 128] f32
    float* out = (float*)d_out;                  // [N, 128] f32

    wint_kernel<<<32, 256>>>(W);
    rowptr_kernel<<<(N_NODES + 1 + 255) / 256, 256>>>(dst);
    gemm_kernel<<<(N_NODES + 31) / 32, 256>>>(feat);
    attn_kernel<<<(N_NODES * 32 + 63) / 64, 64>>>(src, out);
}

// round 11
// speedup vs baseline: 1.1749x; 1.1749x over previous
#include <cuda_runtime.h>
#include <cuda_fp16.h>
#include <cuda_bf16.h>
#include <math_constants.h>

#define N_NODES 50000
#define N_EDGES 1600000
#define IN_SIZE 128
#define NUM_HEADS 4
#define OUT_SIZE 32
// H*D = 128 per node

typedef unsigned long long ull;

// Scratch (device globals — no allocation allowed)
__device__ __half g_h[(size_t)N_NODES * 128];   // projected features fp16 [N,128]
__device__ int    g_rowptr[N_NODES + 1];        // CSR offsets over sorted dst
__device__ ull    g_Wint[64 * 128];             // W interleaved: [k2][c] = (W[2k2][c], W[2k2+1][c])

// ---------------------------------------------------------------------------
// f32x2 helpers (sm_103a; ptxas never auto-fuses — PTX only)
// ---------------------------------------------------------------------------
__device__ __forceinline__ ull fma2(ull a, ull b, ull c) {
    ull d;
    asm("fma.rn.f32x2 %0, %1, %2, %3;" : "=l"(d) : "l"(a), "l"(b), "l"(c));
    return d;
}
__device__ __forceinline__ float2 unpack2(ull u) {
    float2 f;
    f.x = __int_as_float((int)(u & 0xffffffffull));
    f.y = __int_as_float((int)(u >> 32));
    return f;
}
__device__ __forceinline__ unsigned int h2_as_u32(__half2 h) {
    union { __half2 h; unsigned int u; } cvt;
    cvt.h = h;
    return cvt.u;
}

// ---------------------------------------------------------------------------
// Kernel 0: interleave W rows pairwise so the GEMM's f32x2 multiplier is a
// single natural 8B load: g_Wint[k2*128+c] = (W[2k2][c], W[2k2+1][c]).
// 64KB, L1-resident during GEMM. One-time ~1us.
// ---------------------------------------------------------------------------
__global__ void wint_kernel(const float* __restrict__ W) {
    const int idx = blockIdx.x * blockDim.x + threadIdx.x;  // 0..8191
    if (idx >= 64 * 128) return;
    const int k2 = idx >> 7;
    const int c = idx & 127;
    const unsigned int lo = __float_as_uint(__ldg(&W[(2 * k2) * 128 + c]));
    const unsigned int hi = __float_as_uint(__ldg(&W[(2 * k2 + 1) * 128 + c]));
    g_Wint[idx] = (ull)lo | ((ull)hi << 32);
}

// ---------------------------------------------------------------------------
// Kernel 1: h = feat @ W  (50000x128 @ 128x128), fp32 accum via k-split f32x2,
// fp16 output. Block = 256 threads (8 warps), 64 nodes/block; warp owns 8
// nodes. Lane l owns cols {2l, 2l+1, 64+2l, 64+2l+1} so BOTH W loads are
// COALESCED ulonglong2 (16B/lane contiguous -> 4 L1 wavefronts per LDG;
// R10's 2l-indexed loads were stride-32B = 8 wavefronts = L1-bound).
// Accumulator f32x2 lanes hold even-k/odd-k partials (1 FADD at the end),
// so no packing MOVs: feat pair = one LDS.64 broadcast, W pair = natural LDG.
// Per SM per k2: ~128 L1-cyc vs ~128 fma-cyc -> balanced at the ~24us
// FFMA2 chip floor.
// ---------------------------------------------------------------------------
__global__ void __launch_bounds__(256) gemm_kernel(const float* __restrict__ feat) {
    __shared__ float sfeat[64][128];   // 32KB
    const int base = blockIdx.x * 64;
    const int tid = threadIdx.x;

    const int nvalid = min(64, N_NODES - base);
    const float4* fsrc = (const float4*)(feat + (size_t)base * 128);
    for (int i = tid; i < nvalid * 32; i += 256) ((float4*)sfeat)[i] = fsrc[i];
    __syncthreads();

    const int w = tid >> 5;   // warp -> nodes base+8w .. base+8w+7
    const int l = tid & 31;

    ull acc[8][4];  // [node][col group: 2l, 2l+1, 64+2l, 64+2l+1]
#pragma unroll
    for (int n = 0; n < 8; n++)
#pragma unroll
        for (int c = 0; c < 4; c++) acc[n][c] = 0ull;

    const ull* __restrict__ sf = (const ull*)&sfeat[0][0];         // sf[n*64 + k2]
    const ulonglong2* __restrict__ Wp = (const ulonglong2*)g_Wint; // 64 per k2 row

#pragma unroll 2
    for (int k2 = 0; k2 < 64; k2++) {
        const ulonglong2 wa = __ldg(&Wp[k2 * 64 + l]);       // cols 2l, 2l+1
        const ulonglong2 wb = __ldg(&Wp[k2 * 64 + 32 + l]);  // cols 64+2l, 64+2l+1
#pragma unroll
        for (int n = 0; n < 8; n++) {
            const ull f = sf[(w * 8 + n) * 64 + k2];  // (feat[2k2], feat[2k2+1]) bcast
            acc[n][0] = fma2(f, wa.x, acc[n][0]);
            acc[n][1] = fma2(f, wa.y, acc[n][1]);
            acc[n][2] = fma2(f, wb.x, acc[n][2]);
            acc[n][3] = fma2(f, wb.y, acc[n][3]);
        }
    }

    unsigned int* __restrict__ gh32 = (unsigned int*)g_h;  // [node*64 + colpair]
#pragma unroll
    for (int n = 0; n < 8; n++) {
        const int node = base + w * 8 + n;
        if (node < N_NODES) {
            const float2 v0 = unpack2(acc[n][0]);
            const float2 v1 = unpack2(acc[n][1]);
            const float2 v2 = unpack2(acc[n][2]);
            const float2 v3 = unpack2(acc[n][3]);
            // cols 2l,2l+1 -> u32 index node*64 + l ; cols 64+2l.. -> +32+l
            gh32[node * 64 + l]      = h2_as_u32(__floats2half2_rn(v0.x + v0.y, v1.x + v1.y));
            gh32[node * 64 + 32 + l] = h2_as_u32(__floats2half2_rn(v2.x + v2.y, v3.x + v3.y));
        }
    }
}

// ---------------------------------------------------------------------------
// Kernel 2: CSR offsets via binary search (dst is sorted).
// ---------------------------------------------------------------------------
__global__ void rowptr_kernel(const int* __restrict__ dst) {
    const int n = blockIdx.x * blockDim.x + threadIdx.x;
    if (n > N_NODES) return;
    int lo = 0, hi = N_EDGES;
    while (lo < hi) {
        const int mid = (lo + hi) >> 1;
        if (__ldg(&dst[mid]) < n) lo = mid + 1;
        else hi = mid;
    }
    g_rowptr[n] = lo;
}

// ---------------------------------------------------------------------------
// Kernel 3: fused scores + softmax + aggregation. One warp per dst node,
// 64-thread blocks (2 warps) to cut Poisson-degree imbalance at CTA scope.
// fp16 gathers (256B/warp/edge), fp32 math. hd pre-scaled by log2e/sqrt(D)
// so exp = single EX2. Explicit 4-deep gather pipeline for MLP.
// (Measured 60.1us, issue=76.5% — unchanged this round.)
// ---------------------------------------------------------------------------
__global__ void __launch_bounds__(64) attn_kernel(const int* __restrict__ src,
                                                  float* __restrict__ out) {
    const int n = (int)((blockIdx.x * blockDim.x + threadIdx.x) >> 5);
    const int l = threadIdx.x & 31;
    if (n >= N_NODES) return;

    const int beg = g_rowptr[n];
    const int end = g_rowptr[n + 1];

    const uint2* __restrict__ H2 = (const uint2*)g_h;

    // 1/sqrt(32) * log2(e): fold softmax scale + exp2 conversion into hd
    const float scale_d = 0.17677669529663689f * 1.4426950408889634f;
    float2 hd0, hd1;
    {
        const uint2 v = H2[n * 32 + l];
        const float2 a = __half22float2(*(const half2*)&v.x);
        const float2 b = __half22float2(*(const half2*)&v.y);
        hd0.x = a.x * scale_d; hd0.y = a.y * scale_d;
        hd1.x = b.x * scale_d; hd1.y = b.y * scale_d;
    }

    float s = 0.f;
    float2 acc0 = make_float2(0.f, 0.f);
    float2 acc1 = make_float2(0.f, 0.f);

    int e = beg;
    for (; e + 4 <= end; e += 4) {
        int sn[4];
#pragma unroll
        for (int j = 0; j < 4; j++) sn[j] = __ldg(&src[e + j]);
        uint2 v[4];
#pragma unroll
        for (int j = 0; j < 4; j++) v[j] = __ldg(&H2[sn[j] * 32 + l]);
#pragma unroll
        for (int j = 0; j < 4; j++) {
            const float2 a = __half22float2(*(const half2*)&v[j].x);
            const float2 b = __half22float2(*(const half2*)&v[j].y);
            float d = a.x * hd0.x;
            d = fmaf(a.y, hd0.y, d);
            d = fmaf(b.x, hd1.x, d);
            d = fmaf(b.y, hd1.y, d);
            d += __shfl_xor_sync(0xffffffffu, d, 1);
            d += __shfl_xor_sync(0xffffffffu, d, 2);
            d += __shfl_xor_sync(0xffffffffu, d, 4);
            const float p = exp2f(d);   // single MUFU.EX2
            s += p;
            acc0.x = fmaf(p, a.x, acc0.x);
            acc0.y = fmaf(p, a.y, acc0.y);
            acc1.x = fmaf(p, b.x, acc1.x);
            acc1.y = fmaf(p, b.y, acc1.y);
        }
    }
    for (; e < end; e++) {
        const int sn = __ldg(&src[e]);
        const uint2 v = __ldg(&H2[sn * 32 + l]);
        const float2 a = __half22float2(*(const half2*)&v.x);
        const float2 b = __half22float2(*(const half2*)&v.y);
        float d = a.x * hd0.x;
        d = fmaf(a.y, hd0.y, d);
        d = fmaf(b.x, hd1.x, d);
        d = fmaf(b.y, hd1.y, d);
        d += __shfl_xor_sync(0xffffffffu, d, 1);
        d += __shfl_xor_sync(0xffffffffu, d, 2);
        d += __shfl_xor_sync(0xffffffffu, d, 4);
        const float p = exp2f(d);
        s += p;
        acc0.x = fmaf(p, a.x, acc0.x);
        acc0.y = fmaf(p, a.y, acc0.y);
        acc1.x = fmaf(p, b.x, acc1.x);
        acc1.y = fmaf(p, b.y, acc1.y);
    }

    const float inv = (s > 0.f) ? (1.0f / s) : 0.f;
    float4 o;
    o.x = acc0.x * inv; o.y = acc0.y * inv;
    o.z = acc1.x * inv; o.w = acc1.y * inv;
    ((float4*)out)[n * 32 + l] = o;
}

// ---------------------------------------------------------------------------
extern "C" void kernel_launch(void* const* d_in, const int* in_sizes, int n_in,
                              void* d_out, int out_size) {
    const float* feat = (const float*)d_in[0];   // [N, 128] f32
    const int*   src  = (const int*)d_in[1];     // [E] i32
    const int*   dst  = (const int*)d_in[2];     // [E] i32, sorted
    const float* W    = (const float*)d_in[3];   // [128, 128] f32
    float* out = (float*)d_out;                  // [N, 128] f32

    wint_kernel<<<32, 256>>>(W);
    rowptr_kernel<<<(N_NODES + 1 + 255) / 256, 256>>>(dst);
    gemm_kernel<<<(N_NODES + 63) / 64, 256>>>(feat);
    attn_kernel<<<(N_NODES * 32 + 63) / 64, 64>>>(src, out);
}